// round 6
// baseline (speedup 1.0000x reference)
#include <cuda_runtime.h>
#include <cstdint>
#include <cstddef>

#define N_NODES 100000
#define N_EDGES 3200000
#define D_IN    512
#define D_HID   256
#define D_OUT   64

// Scratch (allocation-free rule: __device__ globals)
__device__ float g_support1[(size_t)N_NODES * D_HID];  // x @ w1
__device__ float g_agg1[(size_t)N_NODES * D_HID];      // spmm1 + b1
__device__ float g_support2[(size_t)N_NODES * D_OUT];  // relu(agg1) @ w2

// ---------------------------------------------------------------------------
// Tiled fp32 GEMM: C[M,N] = op(A)[M,K] @ B[K,N], op = identity or relu.
// BM=128, BN=64, BK=16, 256 threads, 8x4 per-thread tile, float4 I/O.
// ---------------------------------------------------------------------------
template <bool RELU_A>
__global__ __launch_bounds__(256, 2)
void gemm_tiled(const float* __restrict__ A, const float* __restrict__ B,
                float* __restrict__ C, int M, int N, int K)
{
    constexpr int BM = 128, BN = 64, BK = 16, TM = 8, TN = 4;
    __shared__ float As[BK][BM];   // transposed A tile
    __shared__ float Bs[BK][BN];

    const int tid = threadIdx.x;
    const int ty  = tid >> 4;   // 0..15 -> 8 rows each
    const int tx  = tid & 15;   // 0..15 -> 4 cols each
    const int row0 = blockIdx.y * BM;
    const int col0 = blockIdx.x * BN;

    float acc[TM][TN];
#pragma unroll
    for (int i = 0; i < TM; i++)
#pragma unroll
        for (int j = 0; j < TN; j++) acc[i][j] = 0.f;

    for (int k0 = 0; k0 < K; k0 += BK) {
        // A tile: 128 rows x 16 cols = 512 float4, 2 per thread
#pragma unroll
        for (int l = 0; l < 2; l++) {
            int idx = tid + l * 256;
            int r   = idx >> 2;            // / (BK/4)
            int c4  = (idx & 3) << 2;
            int gr  = row0 + r;
            float4 v = make_float4(0.f, 0.f, 0.f, 0.f);
            if (gr < M)
                v = *reinterpret_cast<const float4*>(A + (size_t)gr * K + k0 + c4);
            if (RELU_A) {
                v.x = fmaxf(v.x, 0.f); v.y = fmaxf(v.y, 0.f);
                v.z = fmaxf(v.z, 0.f); v.w = fmaxf(v.w, 0.f);
            }
            As[c4 + 0][r] = v.x; As[c4 + 1][r] = v.y;
            As[c4 + 2][r] = v.z; As[c4 + 3][r] = v.w;
        }
        // B tile: 16 rows x 64 cols = 256 float4, 1 per thread
        {
            int r  = tid >> 4;
            int c4 = (tid & 15) << 2;
            float4 v = *reinterpret_cast<const float4*>(
                B + (size_t)(k0 + r) * N + col0 + c4);
            *reinterpret_cast<float4*>(&Bs[r][c4]) = v;
        }
        __syncthreads();

#pragma unroll
        for (int k = 0; k < BK; k++) {
            float ra[TM], rb[TN];
#pragma unroll
            for (int i = 0; i < TM; i++) ra[i] = As[k][ty * TM + i];
#pragma unroll
            for (int j = 0; j < TN; j++) rb[j] = Bs[k][tx * TN + j];
#pragma unroll
            for (int i = 0; i < TM; i++)
#pragma unroll
                for (int j = 0; j < TN; j++)
                    acc[i][j] = fmaf(ra[i], rb[j], acc[i][j]);
        }
        __syncthreads();
    }

#pragma unroll
    for (int i = 0; i < TM; i++) {
        int gr = row0 + ty * TM + i;
        if (gr < M) {
            float4 v = make_float4(acc[i][0], acc[i][1], acc[i][2], acc[i][3]);
            *reinterpret_cast<float4*>(C + (size_t)gr * N + col0 + tx * TN) = v;
        }
    }
}

// ---------------------------------------------------------------------------
// dst[n, 0:D] = b[0:D] for all n (bias-initialized accumulator). float4 form.
// ---------------------------------------------------------------------------
__global__ void init_bias(float* __restrict__ dst, const float* __restrict__ b,
                          int d4, size_t total4)
{
    size_t i = (size_t)blockIdx.x * blockDim.x + threadIdx.x;
    if (i >= total4) return;
    float4 v = reinterpret_cast<const float4*>(b)[i % d4];
    reinterpret_cast<float4*>(dst)[i] = v;
}

// ---------------------------------------------------------------------------
// SpMM layer 1: 256 dims per edge, 64 threads/edge (float4 each), 4 edges/block
// Indices are int32 (JAX x64-disabled coerces the reference's int64 to int32).
// ---------------------------------------------------------------------------
__global__ __launch_bounds__(256)
void spmm_256(const int* __restrict__ row, const int* __restrict__ col,
              const float* __restrict__ ew, const float* __restrict__ sup,
              float* __restrict__ agg)
{
    int lane = threadIdx.x & 63;
    int e = blockIdx.x * 4 + (threadIdx.x >> 6);
    int r = row[e];
    int c = col[e];
    float w = ew[e];
    float4 v = reinterpret_cast<const float4*>(sup + (size_t)c * D_HID)[lane];
    float* dst = agg + (size_t)r * D_HID + lane * 4;
    atomicAdd(dst + 0, w * v.x);
    atomicAdd(dst + 1, w * v.y);
    atomicAdd(dst + 2, w * v.z);
    atomicAdd(dst + 3, w * v.w);
}

// ---------------------------------------------------------------------------
// SpMM layer 2: 64 dims per edge, 16 threads/edge (float4 each), 16 edges/block
// ---------------------------------------------------------------------------
__global__ __launch_bounds__(256)
void spmm_64(const int* __restrict__ row, const int* __restrict__ col,
             const float* __restrict__ ew, const float* __restrict__ sup,
             float* __restrict__ agg)
{
    int lane = threadIdx.x & 15;
    int e = blockIdx.x * 16 + (threadIdx.x >> 4);
    int r = row[e];
    int c = col[e];
    float w = ew[e];
    float4 v = reinterpret_cast<const float4*>(sup + (size_t)c * D_OUT)[lane];
    float* dst = agg + (size_t)r * D_OUT + lane * 4;
    atomicAdd(dst + 0, w * v.x);
    atomicAdd(dst + 1, w * v.y);
    atomicAdd(dst + 2, w * v.z);
    atomicAdd(dst + 3, w * v.w);
}

// ---------------------------------------------------------------------------
// In-place log_softmax over 64 columns. One warp per node, 2 floats per lane.
// ---------------------------------------------------------------------------
__global__ __launch_bounds__(256)
void log_softmax_64(float* __restrict__ out)
{
    int node = blockIdx.x * 8 + (threadIdx.x >> 5);
    if (node >= N_NODES) return;
    int lane = threadIdx.x & 31;
    float2* p = reinterpret_cast<float2*>(out + (size_t)node * D_OUT) + lane;
    float2 v = *p;
    float m = fmaxf(v.x, v.y);
#pragma unroll
    for (int o = 16; o; o >>= 1) m = fmaxf(m, __shfl_xor_sync(0xffffffffu, m, o));
    float s = __expf(v.x - m) + __expf(v.y - m);
#pragma unroll
    for (int o = 16; o; o >>= 1) s += __shfl_xor_sync(0xffffffffu, s, o);
    float lse = m + logf(s);
    v.x -= lse; v.y -= lse;
    *p = v;
}

// ---------------------------------------------------------------------------
extern "C" void kernel_launch(void* const* d_in, const int* in_sizes, int n_in,
                              void* d_out, int out_size)
{
    const float* x   = (const float*)d_in[0];
    const int*   row = (const int*)d_in[1];
    const int*   col = (const int*)d_in[2];
    const float* ew  = (const float*)d_in[3];
    const float* w1  = (const float*)d_in[4];
    const float* b1  = (const float*)d_in[5];
    const float* w2  = (const float*)d_in[6];
    const float* b2  = (const float*)d_in[7];
    float*       out = (float*)d_out;

    float *sup1, *agg1, *sup2;
    cudaGetSymbolAddress((void**)&sup1, g_support1);
    cudaGetSymbolAddress((void**)&agg1, g_agg1);
    cudaGetSymbolAddress((void**)&sup2, g_support2);

    // Layer 1: support1 = x @ w1
    {
        dim3 grid(D_HID / 64, (N_NODES + 127) / 128);
        gemm_tiled<false><<<grid, 256>>>(x, w1, sup1, N_NODES, D_HID, D_IN);
    }
    // agg1 = b1 (bias folded into accumulator init)
    {
        size_t total4 = (size_t)N_NODES * D_HID / 4;
        init_bias<<<(unsigned)((total4 + 255) / 256), 256>>>(agg1, b1, D_HID / 4, total4);
    }
    // agg1 += scatter(ew * support1[col]) by row
    spmm_256<<<N_EDGES / 4, 256>>>(row, col, ew, sup1, agg1);

    // Layer 2: support2 = relu(agg1) @ w2   (relu fused into A load)
    {
        dim3 grid(D_OUT / 64, (N_NODES + 127) / 128);
        gemm_tiled<true><<<grid, 256>>>(agg1, w2, sup2, N_NODES, D_OUT, D_HID);
    }
    // out = b2
    {
        size_t total4 = (size_t)N_NODES * D_OUT / 4;
        init_bias<<<(unsigned)((total4 + 255) / 256), 256>>>(out, b2, D_OUT / 4, total4);
    }
    spmm_64<<<N_EDGES / 16, 256>>>(row, col, ew, sup2, out);

    // log_softmax in-place on out
    log_softmax_64<<<(N_NODES + 7) / 8, 256>>>(out);
}

// round 7
// speedup vs baseline: 2.7464x; 2.7464x over previous
#include <cuda_runtime.h>
#include <cstdint>
#include <cstddef>

#define N_NODES 100000
#define N_EDGES 3200000
#define D_IN    512
#define D_HID   256
#define D_OUT   64

#define SCAN_BLK   512
#define SCAN_ITEMS 8
#define SCAN_TILE  (SCAN_BLK * SCAN_ITEMS)                 // 4096
#define SCAN_NB    ((N_NODES + SCAN_TILE - 1) / SCAN_TILE) // 25

// Scratch (allocation-free rule: __device__ globals)
__device__ float g_support1[(size_t)N_NODES * D_HID];  // x @ w1
__device__ float g_agg1[(size_t)N_NODES * D_HID];      // relu(spmm1 + b1)
__device__ float g_support2[(size_t)N_NODES * D_OUT];  // agg1 @ w2
__device__ int   g_cnt[N_NODES];                       // per-row degree
__device__ int   g_off[N_NODES];                       // fill cursors
__device__ int   g_ptr[N_NODES];                       // CSR row starts (exclusive scan)
__device__ int   g_bsum[SCAN_NB];                      // scan block sums
__device__ int   g_ecol[N_EDGES];                      // edge cols, grouped by row
__device__ float g_eew[N_EDGES];                       // edge weights, grouped by row

// ---------------------------------------------------------------------------
// Tiled fp32 GEMM: C[M,N] = A[M,K] @ B[K,N].
// BM=128, BN=64, BK=16, 256 threads, 8x4 per-thread tile, float4 I/O.
// ---------------------------------------------------------------------------
__global__ __launch_bounds__(256, 2)
void gemm_tiled(const float* __restrict__ A, const float* __restrict__ B,
                float* __restrict__ C, int M, int N, int K)
{
    constexpr int BM = 128, BN = 64, BK = 16, TM = 8, TN = 4;
    __shared__ float As[BK][BM];   // transposed A tile
    __shared__ float Bs[BK][BN];

    const int tid = threadIdx.x;
    const int ty  = tid >> 4;
    const int tx  = tid & 15;
    const int row0 = blockIdx.y * BM;
    const int col0 = blockIdx.x * BN;

    float acc[TM][TN];
#pragma unroll
    for (int i = 0; i < TM; i++)
#pragma unroll
        for (int j = 0; j < TN; j++) acc[i][j] = 0.f;

    for (int k0 = 0; k0 < K; k0 += BK) {
#pragma unroll
        for (int l = 0; l < 2; l++) {
            int idx = tid + l * 256;
            int r   = idx >> 2;
            int c4  = (idx & 3) << 2;
            int gr  = row0 + r;
            float4 v = make_float4(0.f, 0.f, 0.f, 0.f);
            if (gr < M)
                v = *reinterpret_cast<const float4*>(A + (size_t)gr * K + k0 + c4);
            As[c4 + 0][r] = v.x; As[c4 + 1][r] = v.y;
            As[c4 + 2][r] = v.z; As[c4 + 3][r] = v.w;
        }
        {
            int r  = tid >> 4;
            int c4 = (tid & 15) << 2;
            float4 v = *reinterpret_cast<const float4*>(
                B + (size_t)(k0 + r) * N + col0 + c4);
            *reinterpret_cast<float4*>(&Bs[r][c4]) = v;
        }
        __syncthreads();

#pragma unroll
        for (int k = 0; k < BK; k++) {
            float ra[TM], rb[TN];
#pragma unroll
            for (int i = 0; i < TM; i++) ra[i] = As[k][ty * TM + i];
#pragma unroll
            for (int j = 0; j < TN; j++) rb[j] = Bs[k][tx * TN + j];
#pragma unroll
            for (int i = 0; i < TM; i++)
#pragma unroll
                for (int j = 0; j < TN; j++)
                    acc[i][j] = fmaf(ra[i], rb[j], acc[i][j]);
        }
        __syncthreads();
    }

#pragma unroll
    for (int i = 0; i < TM; i++) {
        int gr = row0 + ty * TM + i;
        if (gr < M) {
            float4 v = make_float4(acc[i][0], acc[i][1], acc[i][2], acc[i][3]);
            *reinterpret_cast<float4*>(C + (size_t)gr * N + col0 + tx * TN) = v;
        }
    }
}

// ---------------------------------------------------------------------------
// CSR build kernels
// ---------------------------------------------------------------------------
__global__ void zero_counts()
{
    int i = blockIdx.x * blockDim.x + threadIdx.x;
    if (i < N_NODES) { g_cnt[i] = 0; g_off[i] = 0; }
}

__global__ void histogram(const int* __restrict__ row)
{
    int e = blockIdx.x * blockDim.x + threadIdx.x;
    if (e < N_EDGES) atomicAdd(&g_cnt[row[e]], 1);
}

// Per-block exclusive scan over 4096 counts; writes block sum.
__global__ __launch_bounds__(SCAN_BLK)
void scan_blocks()
{
    __shared__ int s[SCAN_BLK];
    int t = threadIdx.x;
    int base = blockIdx.x * SCAN_TILE + t * SCAN_ITEMS;

    int local[SCAN_ITEMS];
    int sum = 0;
#pragma unroll
    for (int i = 0; i < SCAN_ITEMS; i++) {
        int idx = base + i;
        int v = (idx < N_NODES) ? g_cnt[idx] : 0;
        local[i] = sum;
        sum += v;
    }
    s[t] = sum;
    __syncthreads();
    for (int off = 1; off < SCAN_BLK; off <<= 1) {
        int v = (t >= off) ? s[t - off] : 0;
        __syncthreads();
        s[t] += v;
        __syncthreads();
    }
    int prefix = (t > 0) ? s[t - 1] : 0;
#pragma unroll
    for (int i = 0; i < SCAN_ITEMS; i++) {
        int idx = base + i;
        if (idx < N_NODES) g_ptr[idx] = prefix + local[i];
    }
    if (t == SCAN_BLK - 1) g_bsum[blockIdx.x] = s[t];
}

__global__ void scan_sums()
{
    if (threadIdx.x == 0) {
        int acc = 0;
        for (int i = 0; i < SCAN_NB; i++) {
            int v = g_bsum[i];
            g_bsum[i] = acc;
            acc += v;
        }
    }
}

__global__ __launch_bounds__(SCAN_BLK)
void add_offsets()
{
    int add = g_bsum[blockIdx.x];
    int base = blockIdx.x * SCAN_TILE + threadIdx.x * SCAN_ITEMS;
#pragma unroll
    for (int i = 0; i < SCAN_ITEMS; i++) {
        int idx = base + i;
        if (idx < N_NODES) g_ptr[idx] += add;
    }
}

__global__ void fill_csr(const int* __restrict__ row, const int* __restrict__ col,
                         const float* __restrict__ ew)
{
    int e = blockIdx.x * blockDim.x + threadIdx.x;
    if (e >= N_EDGES) return;
    int r = row[e];
    int p = g_ptr[r] + atomicAdd(&g_off[r], 1);
    g_ecol[p] = col[e];
    g_eew[p]  = ew[e];
}

// ---------------------------------------------------------------------------
// SpMM layer 1 (CSR, no atomics): one warp per row, lane holds 2x float4.
// Epilogue: + b1, relu, store.
// ---------------------------------------------------------------------------
__global__ __launch_bounds__(256)
void spmm1_csr(const float* __restrict__ sup, const float* __restrict__ b1,
               float* __restrict__ agg)
{
    int r = (blockIdx.x * 256 + threadIdx.x) >> 5;
    if (r >= N_NODES) return;
    int lane = threadIdx.x & 31;
    int start = g_ptr[r];
    int n     = g_cnt[r];

    float4 a0 = make_float4(0.f, 0.f, 0.f, 0.f);
    float4 a1 = make_float4(0.f, 0.f, 0.f, 0.f);
    for (int i = 0; i < n; i++) {
        int   c = g_ecol[start + i];
        float w = g_eew[start + i];
        const float4* s = reinterpret_cast<const float4*>(sup + (size_t)c * D_HID);
        float4 v0 = s[lane];
        float4 v1 = s[lane + 32];
        a0.x = fmaf(w, v0.x, a0.x); a0.y = fmaf(w, v0.y, a0.y);
        a0.z = fmaf(w, v0.z, a0.z); a0.w = fmaf(w, v0.w, a0.w);
        a1.x = fmaf(w, v1.x, a1.x); a1.y = fmaf(w, v1.y, a1.y);
        a1.z = fmaf(w, v1.z, a1.z); a1.w = fmaf(w, v1.w, a1.w);
    }
    const float4* bb = reinterpret_cast<const float4*>(b1);
    float4 bv0 = bb[lane], bv1 = bb[lane + 32];
    a0.x = fmaxf(a0.x + bv0.x, 0.f); a0.y = fmaxf(a0.y + bv0.y, 0.f);
    a0.z = fmaxf(a0.z + bv0.z, 0.f); a0.w = fmaxf(a0.w + bv0.w, 0.f);
    a1.x = fmaxf(a1.x + bv1.x, 0.f); a1.y = fmaxf(a1.y + bv1.y, 0.f);
    a1.z = fmaxf(a1.z + bv1.z, 0.f); a1.w = fmaxf(a1.w + bv1.w, 0.f);

    float4* dst = reinterpret_cast<float4*>(agg + (size_t)r * D_HID);
    dst[lane]      = a0;
    dst[lane + 32] = a1;
}

// ---------------------------------------------------------------------------
// SpMM layer 2 (CSR) + bias + log_softmax fused: one warp per row,
// lane holds float2 (64 dims).
// ---------------------------------------------------------------------------
__global__ __launch_bounds__(256)
void spmm2_lsm(const float* __restrict__ sup, const float* __restrict__ b2,
               float* __restrict__ out)
{
    int r = (blockIdx.x * 256 + threadIdx.x) >> 5;
    if (r >= N_NODES) return;
    int lane = threadIdx.x & 31;
    int start = g_ptr[r];
    int n     = g_cnt[r];

    float2 a = make_float2(0.f, 0.f);
    for (int i = 0; i < n; i++) {
        int   c = g_ecol[start + i];
        float w = g_eew[start + i];
        float2 v = reinterpret_cast<const float2*>(sup + (size_t)c * D_OUT)[lane];
        a.x = fmaf(w, v.x, a.x);
        a.y = fmaf(w, v.y, a.y);
    }
    float2 bv = reinterpret_cast<const float2*>(b2)[lane];
    a.x += bv.x;
    a.y += bv.y;

    float m = fmaxf(a.x, a.y);
#pragma unroll
    for (int o = 16; o; o >>= 1) m = fmaxf(m, __shfl_xor_sync(0xffffffffu, m, o));
    float s = __expf(a.x - m) + __expf(a.y - m);
#pragma unroll
    for (int o = 16; o; o >>= 1) s += __shfl_xor_sync(0xffffffffu, s, o);
    float lse = m + logf(s);

    float2 res = make_float2(a.x - lse, a.y - lse);
    reinterpret_cast<float2*>(out + (size_t)r * D_OUT)[lane] = res;
}

// ---------------------------------------------------------------------------
extern "C" void kernel_launch(void* const* d_in, const int* in_sizes, int n_in,
                              void* d_out, int out_size)
{
    const float* x   = (const float*)d_in[0];
    const int*   row = (const int*)d_in[1];
    const int*   col = (const int*)d_in[2];
    const float* ew  = (const float*)d_in[3];
    const float* w1  = (const float*)d_in[4];
    const float* b1  = (const float*)d_in[5];
    const float* w2  = (const float*)d_in[6];
    const float* b2  = (const float*)d_in[7];
    float*       out = (float*)d_out;

    float *sup1, *agg1, *sup2;
    cudaGetSymbolAddress((void**)&sup1, g_support1);
    cudaGetSymbolAddress((void**)&agg1, g_agg1);
    cudaGetSymbolAddress((void**)&sup2, g_support2);

    // --- CSR build (reused by both layers) ---
    zero_counts<<<(N_NODES + 255) / 256, 256>>>();
    histogram<<<(N_EDGES + 255) / 256, 256>>>(row);
    scan_blocks<<<SCAN_NB, SCAN_BLK>>>();
    scan_sums<<<1, 32>>>();
    add_offsets<<<SCAN_NB, SCAN_BLK>>>();
    fill_csr<<<(N_EDGES + 255) / 256, 256>>>(row, col, ew);

    // --- Layer 1: support1 = x @ w1 (overlaps nothing; same stream) ---
    {
        dim3 grid(D_HID / 64, (N_NODES + 127) / 128);
        gemm_tiled<<<grid, 256>>>(x, w1, sup1, N_NODES, D_HID, D_IN);
    }
    // agg1 = relu(segment_sum(ew * sup1[col]) + b1), no atomics
    spmm1_csr<<<(N_NODES * 32 + 255) / 256, 256>>>(sup1, b1, agg1);

    // --- Layer 2: support2 = agg1 @ w2 (relu already applied) ---
    {
        dim3 grid(D_OUT / 64, (N_NODES + 127) / 128);
        gemm_tiled<<<grid, 256>>>(agg1, w2, sup2, N_NODES, D_OUT, D_HID);
    }
    // out = log_softmax(segment_sum(ew * sup2[col]) + b2)
    spmm2_lsm<<<(N_NODES * 32 + 255) / 256, 256>>>(sup2, b2, out);
}

// round 8
// speedup vs baseline: 2.7610x; 1.0053x over previous
#include <cuda_runtime.h>
#include <cstdint>
#include <cstddef>

#define N_NODES 100000
#define N_EDGES 3200000
#define D_IN    512
#define D_HID   256
#define D_OUT   64

#define SCAN_BLK   512
#define SCAN_ITEMS 8
#define SCAN_TILE  (SCAN_BLK * SCAN_ITEMS)                 // 4096
#define SCAN_NB    ((N_NODES + SCAN_TILE - 1) / SCAN_TILE) // 25

// Scratch (allocation-free rule: __device__ globals)
__device__ float g_support1[(size_t)N_NODES * D_HID];  // x @ w1
__device__ float g_agg1[(size_t)N_NODES * D_HID];      // relu(spmm1 + b1)
__device__ float g_support2[(size_t)N_NODES * D_OUT];  // agg1 @ w2
__device__ int   g_cnt[N_NODES];                       // per-row degree
__device__ int   g_off[N_NODES];                       // fill cursors
__device__ int   g_ptr[N_NODES];                       // CSR row starts (exclusive scan)
__device__ int   g_bsum[SCAN_NB];                      // scan block sums
__device__ int   g_ecol[N_EDGES];                      // edge cols, grouped by row
__device__ float g_eew[N_EDGES];                       // edge weights, grouped by row

// ---------------------------------------------------------------------------
// Tiled fp32 GEMM: C[M,N] = A[M,K] @ B[K,N].
// BM=128, BN=64, BK=16, 256 threads, 8x4 per-thread tile, float4 I/O.
// ---------------------------------------------------------------------------
__global__ __launch_bounds__(256, 2)
void gemm_tiled(const float* __restrict__ A, const float* __restrict__ B,
                float* __restrict__ C, int M, int N, int K)
{
    constexpr int BM = 128, BN = 64, BK = 16, TM = 8, TN = 4;
    __shared__ float As[BK][BM];   // transposed A tile
    __shared__ float Bs[BK][BN];

    const int tid = threadIdx.x;
    const int ty  = tid >> 4;
    const int tx  = tid & 15;
    const int row0 = blockIdx.y * BM;
    const int col0 = blockIdx.x * BN;

    float acc[TM][TN];
#pragma unroll
    for (int i = 0; i < TM; i++)
#pragma unroll
        for (int j = 0; j < TN; j++) acc[i][j] = 0.f;

    for (int k0 = 0; k0 < K; k0 += BK) {
#pragma unroll
        for (int l = 0; l < 2; l++) {
            int idx = tid + l * 256;
            int r   = idx >> 2;
            int c4  = (idx & 3) << 2;
            int gr  = row0 + r;
            float4 v = make_float4(0.f, 0.f, 0.f, 0.f);
            if (gr < M)
                v = *reinterpret_cast<const float4*>(A + (size_t)gr * K + k0 + c4);
            As[c4 + 0][r] = v.x; As[c4 + 1][r] = v.y;
            As[c4 + 2][r] = v.z; As[c4 + 3][r] = v.w;
        }
        {
            int r  = tid >> 4;
            int c4 = (tid & 15) << 2;
            float4 v = *reinterpret_cast<const float4*>(
                B + (size_t)(k0 + r) * N + col0 + c4);
            *reinterpret_cast<float4*>(&Bs[r][c4]) = v;
        }
        __syncthreads();

#pragma unroll
        for (int k = 0; k < BK; k++) {
            float ra[TM], rb[TN];
#pragma unroll
            for (int i = 0; i < TM; i++) ra[i] = As[k][ty * TM + i];
#pragma unroll
            for (int j = 0; j < TN; j++) rb[j] = Bs[k][tx * TN + j];
#pragma unroll
            for (int i = 0; i < TM; i++)
#pragma unroll
                for (int j = 0; j < TN; j++)
                    acc[i][j] = fmaf(ra[i], rb[j], acc[i][j]);
        }
        __syncthreads();
    }

#pragma unroll
    for (int i = 0; i < TM; i++) {
        int gr = row0 + ty * TM + i;
        if (gr < M) {
            float4 v = make_float4(acc[i][0], acc[i][1], acc[i][2], acc[i][3]);
            *reinterpret_cast<float4*>(C + (size_t)gr * N + col0 + tx * TN) = v;
        }
    }
}

// ---------------------------------------------------------------------------
// CSR build kernels
// ---------------------------------------------------------------------------
__global__ void zero_counts()
{
    int i = blockIdx.x * blockDim.x + threadIdx.x;
    if (i < N_NODES) { g_cnt[i] = 0; g_off[i] = 0; }
}

__global__ void histogram(const int* __restrict__ row)
{
    int e = blockIdx.x * blockDim.x + threadIdx.x;
    if (e < N_EDGES) atomicAdd(&g_cnt[row[e]], 1);
}

// Per-block exclusive scan over 4096 counts; writes block sum.
__global__ __launch_bounds__(SCAN_BLK)
void scan_blocks()
{
    __shared__ int s[SCAN_BLK];
    int t = threadIdx.x;
    int base = blockIdx.x * SCAN_TILE + t * SCAN_ITEMS;

    int local[SCAN_ITEMS];
    int sum = 0;
#pragma unroll
    for (int i = 0; i < SCAN_ITEMS; i++) {
        int idx = base + i;
        int v = (idx < N_NODES) ? g_cnt[idx] : 0;
        local[i] = sum;
        sum += v;
    }
    s[t] = sum;
    __syncthreads();
    for (int off = 1; off < SCAN_BLK; off <<= 1) {
        int v = (t >= off) ? s[t - off] : 0;
        __syncthreads();
        s[t] += v;
        __syncthreads();
    }
    int prefix = (t > 0) ? s[t - 1] : 0;
#pragma unroll
    for (int i = 0; i < SCAN_ITEMS; i++) {
        int idx = base + i;
        if (idx < N_NODES) g_ptr[idx] = prefix + local[i];
    }
    if (t == SCAN_BLK - 1) g_bsum[blockIdx.x] = s[t];
}

__global__ void scan_sums()
{
    if (threadIdx.x == 0) {
        int acc = 0;
        for (int i = 0; i < SCAN_NB; i++) {
            int v = g_bsum[i];
            g_bsum[i] = acc;
            acc += v;
        }
    }
}

__global__ __launch_bounds__(SCAN_BLK)
void add_offsets()
{
    int add = g_bsum[blockIdx.x];
    int base = blockIdx.x * SCAN_TILE + threadIdx.x * SCAN_ITEMS;
#pragma unroll
    for (int i = 0; i < SCAN_ITEMS; i++) {
        int idx = base + i;
        if (idx < N_NODES) g_ptr[idx] += add;
    }
}

__global__ void fill_csr(const int* __restrict__ row, const int* __restrict__ col,
                         const float* __restrict__ ew)
{
    int e = blockIdx.x * blockDim.x + threadIdx.x;
    if (e >= N_EDGES) return;
    int r = row[e];
    int p = g_ptr[r] + atomicAdd(&g_off[r], 1);
    g_ecol[p] = col[e];
    g_eew[p]  = ew[e];
}

// ---------------------------------------------------------------------------
// SpMM layer 1 (CSR, no atomics): one warp per row, lane holds 2x float4.
// Epilogue: + b1, relu, store.
// ---------------------------------------------------------------------------
__global__ __launch_bounds__(256)
void spmm1_csr(const float* __restrict__ sup, const float* __restrict__ b1,
               float* __restrict__ agg)
{
    int r = (blockIdx.x * 256 + threadIdx.x) >> 5;
    if (r >= N_NODES) return;
    int lane = threadIdx.x & 31;
    int start = g_ptr[r];
    int n     = g_cnt[r];

    float4 a0 = make_float4(0.f, 0.f, 0.f, 0.f);
    float4 a1 = make_float4(0.f, 0.f, 0.f, 0.f);
    for (int i = 0; i < n; i++) {
        int   c = g_ecol[start + i];
        float w = g_eew[start + i];
        const float4* s = reinterpret_cast<const float4*>(sup + (size_t)c * D_HID);
        float4 v0 = s[lane];
        float4 v1 = s[lane + 32];
        a0.x = fmaf(w, v0.x, a0.x); a0.y = fmaf(w, v0.y, a0.y);
        a0.z = fmaf(w, v0.z, a0.z); a0.w = fmaf(w, v0.w, a0.w);
        a1.x = fmaf(w, v1.x, a1.x); a1.y = fmaf(w, v1.y, a1.y);
        a1.z = fmaf(w, v1.z, a1.z); a1.w = fmaf(w, v1.w, a1.w);
    }
    const float4* bb = reinterpret_cast<const float4*>(b1);
    float4 bv0 = bb[lane], bv1 = bb[lane + 32];
    a0.x = fmaxf(a0.x + bv0.x, 0.f); a0.y = fmaxf(a0.y + bv0.y, 0.f);
    a0.z = fmaxf(a0.z + bv0.z, 0.f); a0.w = fmaxf(a0.w + bv0.w, 0.f);
    a1.x = fmaxf(a1.x + bv1.x, 0.f); a1.y = fmaxf(a1.y + bv1.y, 0.f);
    a1.z = fmaxf(a1.z + bv1.z, 0.f); a1.w = fmaxf(a1.w + bv1.w, 0.f);

    float4* dst = reinterpret_cast<float4*>(agg + (size_t)r * D_HID);
    dst[lane]      = a0;
    dst[lane + 32] = a1;
}

// ---------------------------------------------------------------------------
// SpMM layer 2 (CSR) + bias + log_softmax fused: one warp per row,
// lane holds float2 (64 dims).
// ---------------------------------------------------------------------------
__global__ __launch_bounds__(256)
void spmm2_lsm(const float* __restrict__ sup, const float* __restrict__ b2,
               float* __restrict__ out)
{
    int r = (blockIdx.x * 256 + threadIdx.x) >> 5;
    if (r >= N_NODES) return;
    int lane = threadIdx.x & 31;
    int start = g_ptr[r];
    int n     = g_cnt[r];

    float2 a = make_float2(0.f, 0.f);
    for (int i = 0; i < n; i++) {
        int   c = g_ecol[start + i];
        float w = g_eew[start + i];
        float2 v = reinterpret_cast<const float2*>(sup + (size_t)c * D_OUT)[lane];
        a.x = fmaf(w, v.x, a.x);
        a.y = fmaf(w, v.y, a.y);
    }
    float2 bv = reinterpret_cast<const float2*>(b2)[lane];
    a.x += bv.x;
    a.y += bv.y;

    float m = fmaxf(a.x, a.y);
#pragma unroll
    for (int o = 16; o; o >>= 1) m = fmaxf(m, __shfl_xor_sync(0xffffffffu, m, o));
    float s = __expf(a.x - m) + __expf(a.y - m);
#pragma unroll
    for (int o = 16; o; o >>= 1) s += __shfl_xor_sync(0xffffffffu, s, o);
    float lse = m + logf(s);

    float2 res = make_float2(a.x - lse, a.y - lse);
    reinterpret_cast<float2*>(out + (size_t)r * D_OUT)[lane] = res;
}

// ---------------------------------------------------------------------------
extern "C" void kernel_launch(void* const* d_in, const int* in_sizes, int n_in,
                              void* d_out, int out_size)
{
    const float* x   = (const float*)d_in[0];
    const int*   row = (const int*)d_in[1];
    const int*   col = (const int*)d_in[2];
    const float* ew  = (const float*)d_in[3];
    const float* w1  = (const float*)d_in[4];
    const float* b1  = (const float*)d_in[5];
    const float* w2  = (const float*)d_in[6];
    const float* b2  = (const float*)d_in[7];
    float*       out = (float*)d_out;

    float *sup1, *agg1, *sup2;
    cudaGetSymbolAddress((void**)&sup1, g_support1);
    cudaGetSymbolAddress((void**)&agg1, g_agg1);
    cudaGetSymbolAddress((void**)&sup2, g_support2);

    // --- CSR build (reused by both layers) ---
    zero_counts<<<(N_NODES + 255) / 256, 256>>>();
    histogram<<<(N_EDGES + 255) / 256, 256>>>(row);
    scan_blocks<<<SCAN_NB, SCAN_BLK>>>();
    scan_sums<<<1, 32>>>();
    add_offsets<<<SCAN_NB, SCAN_BLK>>>();
    fill_csr<<<(N_EDGES + 255) / 256, 256>>>(row, col, ew);

    // --- Layer 1: support1 = x @ w1 (overlaps nothing; same stream) ---
    {
        dim3 grid(D_HID / 64, (N_NODES + 127) / 128);
        gemm_tiled<<<grid, 256>>>(x, w1, sup1, N_NODES, D_HID, D_IN);
    }
    // agg1 = relu(segment_sum(ew * sup1[col]) + b1), no atomics
    spmm1_csr<<<(N_NODES * 32 + 255) / 256, 256>>>(sup1, b1, agg1);

    // --- Layer 2: support2 = agg1 @ w2 (relu already applied) ---
    {
        dim3 grid(D_OUT / 64, (N_NODES + 127) / 128);
        gemm_tiled<<<grid, 256>>>(agg1, w2, sup2, N_NODES, D_OUT, D_HID);
    }
    // out = log_softmax(segment_sum(ew * sup2[col]) + b2)
    spmm2_lsm<<<(N_NODES * 32 + 255) / 256, 256>>>(sup2, b2, out);
}

// round 10
// speedup vs baseline: 4.0786x; 1.4772x over previous
#include <cuda_runtime.h>
#include <cuda_bf16.h>
#include <mma.h>
#include <cstdint>
#include <cstddef>

using namespace nvcuda;

#define N_NODES 100000
#define N_EDGES 3200000
#define D_IN    512
#define D_HID   256
#define D_OUT   64

#define SCAN_BLK   512
#define SCAN_ITEMS 8
#define SCAN_TILE  (SCAN_BLK * SCAN_ITEMS)                 // 4096
#define SCAN_NB    ((N_NODES + SCAN_TILE - 1) / SCAN_TILE) // 25

// ---------------------------------------------------------------------------
// Scratch (allocation-free rule: __device__ globals)
// ---------------------------------------------------------------------------
__device__ float g_support1[(size_t)N_NODES * D_HID];  // x @ w1
__device__ float g_agg1[(size_t)N_NODES * D_HID];      // relu(spmm1 + b1)
__device__ float g_support2[(size_t)N_NODES * D_OUT];  // agg1 @ w2
__device__ int   g_cnt[N_NODES];
__device__ int   g_off[N_NODES];
__device__ int   g_ptr[N_NODES];
__device__ int   g_bsum[SCAN_NB];
__device__ int   g_ecol[N_EDGES];
__device__ float g_eew[N_EDGES];
// bf16 hi/lo split weights, [K][N] row-major (matches wmma row_major matrix_b)
__device__ __nv_bfloat16 g_w1hi[(size_t)D_IN * D_HID];
__device__ __nv_bfloat16 g_w1lo[(size_t)D_IN * D_HID];
__device__ __nv_bfloat16 g_w2hi[(size_t)D_HID * D_OUT];
__device__ __nv_bfloat16 g_w2lo[(size_t)D_HID * D_OUT];

// ---------------------------------------------------------------------------
// WMMA bf16 GEMM with 2-term split compensation (fp32-grade to ~1e-5):
//   C[M, N_DIM] = A[M, K_DIM] @ B[K_DIM, N_DIM]
//   B supplied pre-split as bf16 hi/lo. A split on the fly during smem stage.
// BM=128, BK=32, 8 warps (2 M x 4 N), warp tile 64 x (BN/4), 16x16x16 frags.
// Per fragment-pair: acc += Ahi*Bhi + Ahi*Blo + Alo*Bhi  (lo*lo ~2^-34 dropped)
// ---------------------------------------------------------------------------
template <int K_DIM, int N_DIM, int BN>
__global__ __launch_bounds__(256, 2)
void gemm_wmma(const float* __restrict__ A,
               const __nv_bfloat16* __restrict__ Bhi,
               const __nv_bfloat16* __restrict__ Blo,
               float* __restrict__ C, int M)
{
    constexpr int BM = 128, BK = 32;
    constexpr int AP = BK + 8;        // padded A row (halves): 80B, 16B-aligned
    constexpr int BP = BN + 8;        // padded B row (halves)
    constexpr int NF = BN / 64;       // wmma n-frags per warp (warp_n = BN/4)

    __shared__ __nv_bfloat16 As_hi[BM * AP], As_lo[BM * AP];
    __shared__ __nv_bfloat16 Bs_hi[BK * BP], Bs_lo[BK * BP];

    const int tid     = threadIdx.x;
    const int w       = tid >> 5;
    const int warp_m0 = (w & 1) * 64;
    const int warp_n0 = (w >> 1) * (BN / 4);
    const int row0    = blockIdx.y * BM;
    const int col0    = blockIdx.x * BN;

    wmma::fragment<wmma::accumulator, 16, 16, 16, float> acc[4][NF];
#pragma unroll
    for (int i = 0; i < 4; i++)
#pragma unroll
        for (int j = 0; j < NF; j++) wmma::fill_fragment(acc[i][j], 0.f);

    for (int k0 = 0; k0 < K_DIM; k0 += BK) {
        // ---- A tile: 128x32 fp32 -> bf16 hi/lo (4 float4 per thread) ----
#pragma unroll
        for (int t = 0; t < 4; t++) {
            int idx = tid + t * 256;          // 1024 float4 slots
            int r   = idx >> 3;
            int c4  = (idx & 7) << 2;
            float4 v = make_float4(0.f, 0.f, 0.f, 0.f);
            if (row0 + r < M)
                v = *reinterpret_cast<const float4*>(
                    A + (size_t)(row0 + r) * K_DIM + k0 + c4);
            __nv_bfloat16 hx = __float2bfloat16_rn(v.x);
            __nv_bfloat16 hy = __float2bfloat16_rn(v.y);
            __nv_bfloat16 hz = __float2bfloat16_rn(v.z);
            __nv_bfloat16 hw = __float2bfloat16_rn(v.w);
            int o = r * AP + c4;
            As_hi[o + 0] = hx; As_hi[o + 1] = hy;
            As_hi[o + 2] = hz; As_hi[o + 3] = hw;
            As_lo[o + 0] = __float2bfloat16_rn(v.x - __bfloat162float(hx));
            As_lo[o + 1] = __float2bfloat16_rn(v.y - __bfloat162float(hy));
            As_lo[o + 2] = __float2bfloat16_rn(v.z - __bfloat162float(hz));
            As_lo[o + 3] = __float2bfloat16_rn(v.w - __bfloat162float(hw));
        }
        // ---- B tiles: BKxBN bf16 hi/lo, uint4 (8 halves) per slot ----
#pragma unroll
        for (int idx = tid; idx < BK * BN / 8; idx += 256) {
            int r  = idx / (BN / 8);
            int c8 = (idx % (BN / 8)) * 8;
            size_t go = (size_t)(k0 + r) * N_DIM + col0 + c8;
            int    so = r * BP + c8;
            *reinterpret_cast<uint4*>(&Bs_hi[so]) =
                *reinterpret_cast<const uint4*>(&Bhi[go]);
            *reinterpret_cast<uint4*>(&Bs_lo[so]) =
                *reinterpret_cast<const uint4*>(&Blo[go]);
        }
        __syncthreads();

#pragma unroll
        for (int ks = 0; ks < BK; ks += 16) {
            wmma::fragment<wmma::matrix_b, 16, 16, 16, __nv_bfloat16,
                           wmma::row_major> bh[NF], bl[NF];
#pragma unroll
            for (int j = 0; j < NF; j++) {
                wmma::load_matrix_sync(bh[j], &Bs_hi[ks * BP + warp_n0 + j * 16], BP);
                wmma::load_matrix_sync(bl[j], &Bs_lo[ks * BP + warp_n0 + j * 16], BP);
            }
#pragma unroll
            for (int i = 0; i < 4; i++) {
                wmma::fragment<wmma::matrix_a, 16, 16, 16, __nv_bfloat16,
                               wmma::row_major> ah, al;
                wmma::load_matrix_sync(ah, &As_hi[(warp_m0 + i * 16) * AP + ks], AP);
                wmma::load_matrix_sync(al, &As_lo[(warp_m0 + i * 16) * AP + ks], AP);
#pragma unroll
                for (int j = 0; j < NF; j++) {
                    wmma::mma_sync(acc[i][j], ah, bh[j], acc[i][j]);
                    wmma::mma_sync(acc[i][j], ah, bl[j], acc[i][j]);
                    wmma::mma_sync(acc[i][j], al, bh[j], acc[i][j]);
                }
            }
        }
        __syncthreads();
    }

    // M % 16 == 0, so each 16-row fragment is fully in or fully out of range.
#pragma unroll
    for (int i = 0; i < 4; i++) {
        int gr = row0 + warp_m0 + i * 16;
        if (gr < M) {
#pragma unroll
            for (int j = 0; j < NF; j++)
                wmma::store_matrix_sync(
                    C + (size_t)gr * N_DIM + col0 + warp_n0 + j * 16,
                    acc[i][j], N_DIM, wmma::mem_row_major);
        }
    }
}

// ---------------------------------------------------------------------------
// Elementwise bf16 hi/lo split of a weight matrix (no transpose needed).
// ---------------------------------------------------------------------------
__global__ void split_w(const float* __restrict__ W,
                        __nv_bfloat16* __restrict__ Hi,
                        __nv_bfloat16* __restrict__ Lo, int n)
{
    int i = blockIdx.x * 256 + threadIdx.x;
    if (i >= n) return;
    float v = W[i];
    __nv_bfloat16 h = __float2bfloat16_rn(v);
    Hi[i] = h;
    Lo[i] = __float2bfloat16_rn(v - __bfloat162float(h));
}

// ---------------------------------------------------------------------------
// CSR build kernels (unchanged from R7 winner)
// ---------------------------------------------------------------------------
__global__ void zero_counts()
{
    int i = blockIdx.x * blockDim.x + threadIdx.x;
    if (i < N_NODES) { g_cnt[i] = 0; g_off[i] = 0; }
}

__global__ void histogram(const int* __restrict__ row)
{
    int e = blockIdx.x * blockDim.x + threadIdx.x;
    if (e < N_EDGES) atomicAdd(&g_cnt[row[e]], 1);
}

__global__ __launch_bounds__(SCAN_BLK)
void scan_blocks()
{
    __shared__ int s[SCAN_BLK];
    int t = threadIdx.x;
    int base = blockIdx.x * SCAN_TILE + t * SCAN_ITEMS;

    int local[SCAN_ITEMS];
    int sum = 0;
#pragma unroll
    for (int i = 0; i < SCAN_ITEMS; i++) {
        int idx = base + i;
        int v = (idx < N_NODES) ? g_cnt[idx] : 0;
        local[i] = sum;
        sum += v;
    }
    s[t] = sum;
    __syncthreads();
    for (int off = 1; off < SCAN_BLK; off <<= 1) {
        int v = (t >= off) ? s[t - off] : 0;
        __syncthreads();
        s[t] += v;
        __syncthreads();
    }
    int prefix = (t > 0) ? s[t - 1] : 0;
#pragma unroll
    for (int i = 0; i < SCAN_ITEMS; i++) {
        int idx = base + i;
        if (idx < N_NODES) g_ptr[idx] = prefix + local[i];
    }
    if (t == SCAN_BLK - 1) g_bsum[blockIdx.x] = s[t];
}

__global__ void scan_sums()
{
    if (threadIdx.x == 0) {
        int acc = 0;
        for (int i = 0; i < SCAN_NB; i++) {
            int v = g_bsum[i];
            g_bsum[i] = acc;
            acc += v;
        }
    }
}

__global__ __launch_bounds__(SCAN_BLK)
void add_offsets()
{
    int add = g_bsum[blockIdx.x];
    int base = blockIdx.x * SCAN_TILE + threadIdx.x * SCAN_ITEMS;
#pragma unroll
    for (int i = 0; i < SCAN_ITEMS; i++) {
        int idx = base + i;
        if (idx < N_NODES) g_ptr[idx] += add;
    }
}

__global__ void fill_csr(const int* __restrict__ row, const int* __restrict__ col,
                         const float* __restrict__ ew)
{
    int e = blockIdx.x * blockDim.x + threadIdx.x;
    if (e >= N_EDGES) return;
    int r = row[e];
    int p = g_ptr[r] + atomicAdd(&g_off[r], 1);
    g_ecol[p] = col[e];
    g_eew[p]  = ew[e];
}

// ---------------------------------------------------------------------------
// SpMM layer 1 (CSR, no atomics): one warp per row; + b1, relu fused.
// ---------------------------------------------------------------------------
__global__ __launch_bounds__(256)
void spmm1_csr(const float* __restrict__ sup, const float* __restrict__ b1,
               float* __restrict__ agg)
{
    int r = (blockIdx.x * 256 + threadIdx.x) >> 5;
    if (r >= N_NODES) return;
    int lane = threadIdx.x & 31;
    int start = g_ptr[r];
    int n     = g_cnt[r];

    float4 a0 = make_float4(0.f, 0.f, 0.f, 0.f);
    float4 a1 = make_float4(0.f, 0.f, 0.f, 0.f);
    for (int i = 0; i < n; i++) {
        int   c = g_ecol[start + i];
        float w = g_eew[start + i];
        const float4* s = reinterpret_cast<const float4*>(sup + (size_t)c * D_HID);
        float4 v0 = s[lane];
        float4 v1 = s[lane + 32];
        a0.x = fmaf(w, v0.x, a0.x); a0.y = fmaf(w, v0.y, a0.y);
        a0.z = fmaf(w, v0.z, a0.z); a0.w = fmaf(w, v0.w, a0.w);
        a1.x = fmaf(w, v1.x, a1.x); a1.y = fmaf(w, v1.y, a1.y);
        a1.z = fmaf(w, v1.z, a1.z); a1.w = fmaf(w, v1.w, a1.w);
    }
    const float4* bb = reinterpret_cast<const float4*>(b1);
    float4 bv0 = bb[lane], bv1 = bb[lane + 32];
    a0.x = fmaxf(a0.x + bv0.x, 0.f); a0.y = fmaxf(a0.y + bv0.y, 0.f);
    a0.z = fmaxf(a0.z + bv0.z, 0.f); a0.w = fmaxf(a0.w + bv0.w, 0.f);
    a1.x = fmaxf(a1.x + bv1.x, 0.f); a1.y = fmaxf(a1.y + bv1.y, 0.f);
    a1.z = fmaxf(a1.z + bv1.z, 0.f); a1.w = fmaxf(a1.w + bv1.w, 0.f);

    float4* dst = reinterpret_cast<float4*>(agg + (size_t)r * D_HID);
    dst[lane]      = a0;
    dst[lane + 32] = a1;
}

// ---------------------------------------------------------------------------
// SpMM layer 2 (CSR) + bias + log_softmax fused: one warp per row.
// ---------------------------------------------------------------------------
__global__ __launch_bounds__(256)
void spmm2_lsm(const float* __restrict__ sup, const float* __restrict__ b2,
               float* __restrict__ out)
{
    int r = (blockIdx.x * 256 + threadIdx.x) >> 5;
    if (r >= N_NODES) return;
    int lane = threadIdx.x & 31;
    int start = g_ptr[r];
    int n     = g_cnt[r];

    float2 a = make_float2(0.f, 0.f);
    for (int i = 0; i < n; i++) {
        int   c = g_ecol[start + i];
        float w = g_eew[start + i];
        float2 v = reinterpret_cast<const float2*>(sup + (size_t)c * D_OUT)[lane];
        a.x = fmaf(w, v.x, a.x);
        a.y = fmaf(w, v.y, a.y);
    }
    float2 bv = reinterpret_cast<const float2*>(b2)[lane];
    a.x += bv.x;
    a.y += bv.y;

    float m = fmaxf(a.x, a.y);
#pragma unroll
    for (int o = 16; o; o >>= 1) m = fmaxf(m, __shfl_xor_sync(0xffffffffu, m, o));
    float s = __expf(a.x - m) + __expf(a.y - m);
#pragma unroll
    for (int o = 16; o; o >>= 1) s += __shfl_xor_sync(0xffffffffu, s, o);
    float lse = m + logf(s);

    float2 res = make_float2(a.x - lse, a.y - lse);
    reinterpret_cast<float2*>(out + (size_t)r * D_OUT)[lane] = res;
}

// ---------------------------------------------------------------------------
extern "C" void kernel_launch(void* const* d_in, const int* in_sizes, int n_in,
                              void* d_out, int out_size)
{
    const float* x   = (const float*)d_in[0];
    const int*   row = (const int*)d_in[1];
    const int*   col = (const int*)d_in[2];
    const float* ew  = (const float*)d_in[3];
    const float* w1  = (const float*)d_in[4];
    const float* b1  = (const float*)d_in[5];
    const float* w2  = (const float*)d_in[6];
    const float* b2  = (const float*)d_in[7];
    float*       out = (float*)d_out;

    float *sup1, *agg1, *sup2;
    __nv_bfloat16 *w1hi, *w1lo, *w2hi, *w2lo;
    cudaGetSymbolAddress((void**)&sup1, g_support1);
    cudaGetSymbolAddress((void**)&agg1, g_agg1);
    cudaGetSymbolAddress((void**)&sup2, g_support2);
    cudaGetSymbolAddress((void**)&w1hi, g_w1hi);
    cudaGetSymbolAddress((void**)&w1lo, g_w1lo);
    cudaGetSymbolAddress((void**)&w2hi, g_w2hi);
    cudaGetSymbolAddress((void**)&w2lo, g_w2lo);

    // --- CSR build (reused by both layers) ---
    zero_counts<<<(N_NODES + 255) / 256, 256>>>();
    histogram<<<(N_EDGES + 255) / 256, 256>>>(row);
    scan_blocks<<<SCAN_NB, SCAN_BLK>>>();
    scan_sums<<<1, 32>>>();
    add_offsets<<<SCAN_NB, SCAN_BLK>>>();
    fill_csr<<<(N_EDGES + 255) / 256, 256>>>(row, col, ew);

    // --- Weight bf16 hi/lo split (row-major [K][N], no transpose) ---
    split_w<<<(D_IN * D_HID + 255) / 256, 256>>>(w1, w1hi, w1lo, D_IN * D_HID);
    split_w<<<(D_HID * D_OUT + 255) / 256, 256>>>(w2, w2hi, w2lo, D_HID * D_OUT);

    const int MTILES = (N_NODES + 127) / 128;  // 782

    // --- Layer 1: support1 = x @ w1 (WMMA bf16, 3-pass compensated) ---
    gemm_wmma<D_IN, D_HID, 128><<<dim3(D_HID / 128, MTILES), 256>>>(
        x, w1hi, w1lo, sup1, N_NODES);
    // agg1 = relu(segment_sum(ew * sup1[col]) + b1)
    spmm1_csr<<<(N_NODES * 32 + 255) / 256, 256>>>(sup1, b1, agg1);

    // --- Layer 2: support2 = agg1 @ w2 (WMMA bf16, 3-pass compensated) ---
    gemm_wmma<D_HID, D_OUT, 64><<<dim3(1, MTILES), 256>>>(
        agg1, w2hi, w2lo, sup2, N_NODES);
    // out = log_softmax(segment_sum(ew * sup2[col]) + b2)
    spmm2_lsm<<<(N_NODES * 32 + 255) / 256, 256>>>(sup2, b2, out);
}

// round 11
// speedup vs baseline: 4.1155x; 1.0090x over previous
#include <cuda_runtime.h>
#include <cuda_bf16.h>
#include <mma.h>
#include <cstdint>
#include <cstddef>

using namespace nvcuda;

#define N_NODES 100000
#define N_EDGES 3200000
#define D_IN    512
#define D_HID   256
#define D_OUT   64

#define SCAN_BLK   512
#define SCAN_ITEMS 8
#define SCAN_TILE  (SCAN_BLK * SCAN_ITEMS)                 // 4096
#define SCAN_NB    ((N_NODES + SCAN_TILE - 1) / SCAN_TILE) // 25

// ---------------------------------------------------------------------------
// Scratch (allocation-free rule: __device__ globals)
// ---------------------------------------------------------------------------
__device__ float g_support1[(size_t)N_NODES * D_HID];  // x @ w1
__device__ float g_agg1[(size_t)N_NODES * D_HID];      // relu(spmm1 + b1)
__device__ float g_support2[(size_t)N_NODES * D_OUT];  // agg1 @ w2
__device__ int   g_cnt[N_NODES];
__device__ int   g_off[N_NODES];
__device__ int   g_ptr[N_NODES];
__device__ int   g_bsum[SCAN_NB];
__device__ int   g_ecol[N_EDGES];
__device__ float g_eew[N_EDGES];
// bf16 hi/lo split weights, [K][N] row-major (matches wmma row_major matrix_b)
__device__ __nv_bfloat16 g_w1hi[(size_t)D_IN * D_HID];
__device__ __nv_bfloat16 g_w1lo[(size_t)D_IN * D_HID];
__device__ __nv_bfloat16 g_w2hi[(size_t)D_HID * D_OUT];
__device__ __nv_bfloat16 g_w2lo[(size_t)D_HID * D_OUT];

// ---------------------------------------------------------------------------
// WMMA bf16 GEMM with 2-term split compensation (fp32-grade to ~1e-5):
//   C[M, N_DIM] = A[M, K_DIM] @ B[K_DIM, N_DIM]
//   B supplied pre-split as bf16 hi/lo. A split on the fly during smem stage.
// BM=128, BK=32, 8 warps (2 M x 4 N), warp tile 64 x (BN/4), 16x16x16 frags.
// Per fragment-pair: acc += Ahi*Bhi + Ahi*Blo + Alo*Bhi  (lo*lo ~2^-34 dropped)
// ---------------------------------------------------------------------------
template <int K_DIM, int N_DIM, int BN>
__global__ __launch_bounds__(256, 2)
void gemm_wmma(const float* __restrict__ A,
               const __nv_bfloat16* __restrict__ Bhi,
               const __nv_bfloat16* __restrict__ Blo,
               float* __restrict__ C, int M)
{
    constexpr int BM = 128, BK = 32;
    constexpr int AP = BK + 8;        // padded A row (halves): 80B, 16B-aligned
    constexpr int BP = BN + 8;        // padded B row (halves)
    constexpr int NF = BN / 64;       // wmma n-frags per warp (warp_n = BN/4)

    __shared__ __nv_bfloat16 As_hi[BM * AP], As_lo[BM * AP];
    __shared__ __nv_bfloat16 Bs_hi[BK * BP], Bs_lo[BK * BP];

    const int tid     = threadIdx.x;
    const int w       = tid >> 5;
    const int warp_m0 = (w & 1) * 64;
    const int warp_n0 = (w >> 1) * (BN / 4);
    const int row0    = blockIdx.y * BM;
    const int col0    = blockIdx.x * BN;

    wmma::fragment<wmma::accumulator, 16, 16, 16, float> acc[4][NF];
#pragma unroll
    for (int i = 0; i < 4; i++)
#pragma unroll
        for (int j = 0; j < NF; j++) wmma::fill_fragment(acc[i][j], 0.f);

    for (int k0 = 0; k0 < K_DIM; k0 += BK) {
        // ---- A tile: 128x32 fp32 -> bf16 hi/lo (4 float4 per thread) ----
#pragma unroll
        for (int t = 0; t < 4; t++) {
            int idx = tid + t * 256;          // 1024 float4 slots
            int r   = idx >> 3;
            int c4  = (idx & 7) << 2;
            float4 v = make_float4(0.f, 0.f, 0.f, 0.f);
            if (row0 + r < M)
                v = *reinterpret_cast<const float4*>(
                    A + (size_t)(row0 + r) * K_DIM + k0 + c4);
            __nv_bfloat16 hx = __float2bfloat16_rn(v.x);
            __nv_bfloat16 hy = __float2bfloat16_rn(v.y);
            __nv_bfloat16 hz = __float2bfloat16_rn(v.z);
            __nv_bfloat16 hw = __float2bfloat16_rn(v.w);
            int o = r * AP + c4;
            As_hi[o + 0] = hx; As_hi[o + 1] = hy;
            As_hi[o + 2] = hz; As_hi[o + 3] = hw;
            As_lo[o + 0] = __float2bfloat16_rn(v.x - __bfloat162float(hx));
            As_lo[o + 1] = __float2bfloat16_rn(v.y - __bfloat162float(hy));
            As_lo[o + 2] = __float2bfloat16_rn(v.z - __bfloat162float(hz));
            As_lo[o + 3] = __float2bfloat16_rn(v.w - __bfloat162float(hw));
        }
        // ---- B tiles: BKxBN bf16 hi/lo, uint4 (8 halves) per slot ----
#pragma unroll
        for (int idx = tid; idx < BK * BN / 8; idx += 256) {
            int r  = idx / (BN / 8);
            int c8 = (idx % (BN / 8)) * 8;
            size_t go = (size_t)(k0 + r) * N_DIM + col0 + c8;
            int    so = r * BP + c8;
            *reinterpret_cast<uint4*>(&Bs_hi[so]) =
                *reinterpret_cast<const uint4*>(&Bhi[go]);
            *reinterpret_cast<uint4*>(&Bs_lo[so]) =
                *reinterpret_cast<const uint4*>(&Blo[go]);
        }
        __syncthreads();

#pragma unroll
        for (int ks = 0; ks < BK; ks += 16) {
            wmma::fragment<wmma::matrix_b, 16, 16, 16, __nv_bfloat16,
                           wmma::row_major> bh[NF], bl[NF];
#pragma unroll
            for (int j = 0; j < NF; j++) {
                wmma::load_matrix_sync(bh[j], &Bs_hi[ks * BP + warp_n0 + j * 16], BP);
                wmma::load_matrix_sync(bl[j], &Bs_lo[ks * BP + warp_n0 + j * 16], BP);
            }
#pragma unroll
            for (int i = 0; i < 4; i++) {
                wmma::fragment<wmma::matrix_a, 16, 16, 16, __nv_bfloat16,
                               wmma::row_major> ah, al;
                wmma::load_matrix_sync(ah, &As_hi[(warp_m0 + i * 16) * AP + ks], AP);
                wmma::load_matrix_sync(al, &As_lo[(warp_m0 + i * 16) * AP + ks], AP);
#pragma unroll
                for (int j = 0; j < NF; j++) {
                    wmma::mma_sync(acc[i][j], ah, bh[j], acc[i][j]);
                    wmma::mma_sync(acc[i][j], ah, bl[j], acc[i][j]);
                    wmma::mma_sync(acc[i][j], al, bh[j], acc[i][j]);
                }
            }
        }
        __syncthreads();
    }

    // M % 16 == 0, so each 16-row fragment is fully in or fully out of range.
#pragma unroll
    for (int i = 0; i < 4; i++) {
        int gr = row0 + warp_m0 + i * 16;
        if (gr < M) {
#pragma unroll
            for (int j = 0; j < NF; j++)
                wmma::store_matrix_sync(
                    C + (size_t)gr * N_DIM + col0 + warp_n0 + j * 16,
                    acc[i][j], N_DIM, wmma::mem_row_major);
        }
    }
}

// ---------------------------------------------------------------------------
// Elementwise bf16 hi/lo split of a weight matrix (no transpose needed).
// ---------------------------------------------------------------------------
__global__ void split_w(const float* __restrict__ W,
                        __nv_bfloat16* __restrict__ Hi,
                        __nv_bfloat16* __restrict__ Lo, int n)
{
    int i = blockIdx.x * 256 + threadIdx.x;
    if (i >= n) return;
    float v = W[i];
    __nv_bfloat16 h = __float2bfloat16_rn(v);
    Hi[i] = h;
    Lo[i] = __float2bfloat16_rn(v - __bfloat162float(h));
}

// ---------------------------------------------------------------------------
// CSR build kernels (unchanged from R7 winner)
// ---------------------------------------------------------------------------
__global__ void zero_counts()
{
    int i = blockIdx.x * blockDim.x + threadIdx.x;
    if (i < N_NODES) { g_cnt[i] = 0; g_off[i] = 0; }
}

__global__ void histogram(const int* __restrict__ row)
{
    int e = blockIdx.x * blockDim.x + threadIdx.x;
    if (e < N_EDGES) atomicAdd(&g_cnt[row[e]], 1);
}

__global__ __launch_bounds__(SCAN_BLK)
void scan_blocks()
{
    __shared__ int s[SCAN_BLK];
    int t = threadIdx.x;
    int base = blockIdx.x * SCAN_TILE + t * SCAN_ITEMS;

    int local[SCAN_ITEMS];
    int sum = 0;
#pragma unroll
    for (int i = 0; i < SCAN_ITEMS; i++) {
        int idx = base + i;
        int v = (idx < N_NODES) ? g_cnt[idx] : 0;
        local[i] = sum;
        sum += v;
    }
    s[t] = sum;
    __syncthreads();
    for (int off = 1; off < SCAN_BLK; off <<= 1) {
        int v = (t >= off) ? s[t - off] : 0;
        __syncthreads();
        s[t] += v;
        __syncthreads();
    }
    int prefix = (t > 0) ? s[t - 1] : 0;
#pragma unroll
    for (int i = 0; i < SCAN_ITEMS; i++) {
        int idx = base + i;
        if (idx < N_NODES) g_ptr[idx] = prefix + local[i];
    }
    if (t == SCAN_BLK - 1) g_bsum[blockIdx.x] = s[t];
}

__global__ void scan_sums()
{
    if (threadIdx.x == 0) {
        int acc = 0;
        for (int i = 0; i < SCAN_NB; i++) {
            int v = g_bsum[i];
            g_bsum[i] = acc;
            acc += v;
        }
    }
}

__global__ __launch_bounds__(SCAN_BLK)
void add_offsets()
{
    int add = g_bsum[blockIdx.x];
    int base = blockIdx.x * SCAN_TILE + threadIdx.x * SCAN_ITEMS;
#pragma unroll
    for (int i = 0; i < SCAN_ITEMS; i++) {
        int idx = base + i;
        if (idx < N_NODES) g_ptr[idx] += add;
    }
}

__global__ void fill_csr(const int* __restrict__ row, const int* __restrict__ col,
                         const float* __restrict__ ew)
{
    int e = blockIdx.x * blockDim.x + threadIdx.x;
    if (e >= N_EDGES) return;
    int r = row[e];
    int p = g_ptr[r] + atomicAdd(&g_off[r], 1);
    g_ecol[p] = col[e];
    g_eew[p]  = ew[e];
}

// ---------------------------------------------------------------------------
// SpMM layer 1 (CSR, no atomics): one warp per row; + b1, relu fused.
// ---------------------------------------------------------------------------
__global__ __launch_bounds__(256)
void spmm1_csr(const float* __restrict__ sup, const float* __restrict__ b1,
               float* __restrict__ agg)
{
    int r = (blockIdx.x * 256 + threadIdx.x) >> 5;
    if (r >= N_NODES) return;
    int lane = threadIdx.x & 31;
    int start = g_ptr[r];
    int n     = g_cnt[r];

    float4 a0 = make_float4(0.f, 0.f, 0.f, 0.f);
    float4 a1 = make_float4(0.f, 0.f, 0.f, 0.f);
    for (int i = 0; i < n; i++) {
        int   c = g_ecol[start + i];
        float w = g_eew[start + i];
        const float4* s = reinterpret_cast<const float4*>(sup + (size_t)c * D_HID);
        float4 v0 = s[lane];
        float4 v1 = s[lane + 32];
        a0.x = fmaf(w, v0.x, a0.x); a0.y = fmaf(w, v0.y, a0.y);
        a0.z = fmaf(w, v0.z, a0.z); a0.w = fmaf(w, v0.w, a0.w);
        a1.x = fmaf(w, v1.x, a1.x); a1.y = fmaf(w, v1.y, a1.y);
        a1.z = fmaf(w, v1.z, a1.z); a1.w = fmaf(w, v1.w, a1.w);
    }
    const float4* bb = reinterpret_cast<const float4*>(b1);
    float4 bv0 = bb[lane], bv1 = bb[lane + 32];
    a0.x = fmaxf(a0.x + bv0.x, 0.f); a0.y = fmaxf(a0.y + bv0.y, 0.f);
    a0.z = fmaxf(a0.z + bv0.z, 0.f); a0.w = fmaxf(a0.w + bv0.w, 0.f);
    a1.x = fmaxf(a1.x + bv1.x, 0.f); a1.y = fmaxf(a1.y + bv1.y, 0.f);
    a1.z = fmaxf(a1.z + bv1.z, 0.f); a1.w = fmaxf(a1.w + bv1.w, 0.f);

    float4* dst = reinterpret_cast<float4*>(agg + (size_t)r * D_HID);
    dst[lane]      = a0;
    dst[lane + 32] = a1;
}

// ---------------------------------------------------------------------------
// SpMM layer 2 (CSR) + bias + log_softmax fused: one warp per row.
// ---------------------------------------------------------------------------
__global__ __launch_bounds__(256)
void spmm2_lsm(const float* __restrict__ sup, const float* __restrict__ b2,
               float* __restrict__ out)
{
    int r = (blockIdx.x * 256 + threadIdx.x) >> 5;
    if (r >= N_NODES) return;
    int lane = threadIdx.x & 31;
    int start = g_ptr[r];
    int n     = g_cnt[r];

    float2 a = make_float2(0.f, 0.f);
    for (int i = 0; i < n; i++) {
        int   c = g_ecol[start + i];
        float w = g_eew[start + i];
        float2 v = reinterpret_cast<const float2*>(sup + (size_t)c * D_OUT)[lane];
        a.x = fmaf(w, v.x, a.x);
        a.y = fmaf(w, v.y, a.y);
    }
    float2 bv = reinterpret_cast<const float2*>(b2)[lane];
    a.x += bv.x;
    a.y += bv.y;

    float m = fmaxf(a.x, a.y);
#pragma unroll
    for (int o = 16; o; o >>= 1) m = fmaxf(m, __shfl_xor_sync(0xffffffffu, m, o));
    float s = __expf(a.x - m) + __expf(a.y - m);
#pragma unroll
    for (int o = 16; o; o >>= 1) s += __shfl_xor_sync(0xffffffffu, s, o);
    float lse = m + logf(s);

    float2 res = make_float2(a.x - lse, a.y - lse);
    reinterpret_cast<float2*>(out + (size_t)r * D_OUT)[lane] = res;
}

// ---------------------------------------------------------------------------
extern "C" void kernel_launch(void* const* d_in, const int* in_sizes, int n_in,
                              void* d_out, int out_size)
{
    const float* x   = (const float*)d_in[0];
    const int*   row = (const int*)d_in[1];
    const int*   col = (const int*)d_in[2];
    const float* ew  = (const float*)d_in[3];
    const float* w1  = (const float*)d_in[4];
    const float* b1  = (const float*)d_in[5];
    const float* w2  = (const float*)d_in[6];
    const float* b2  = (const float*)d_in[7];
    float*       out = (float*)d_out;

    float *sup1, *agg1, *sup2;
    __nv_bfloat16 *w1hi, *w1lo, *w2hi, *w2lo;
    cudaGetSymbolAddress((void**)&sup1, g_support1);
    cudaGetSymbolAddress((void**)&agg1, g_agg1);
    cudaGetSymbolAddress((void**)&sup2, g_support2);
    cudaGetSymbolAddress((void**)&w1hi, g_w1hi);
    cudaGetSymbolAddress((void**)&w1lo, g_w1lo);
    cudaGetSymbolAddress((void**)&w2hi, g_w2hi);
    cudaGetSymbolAddress((void**)&w2lo, g_w2lo);

    // --- CSR build (reused by both layers) ---
    zero_counts<<<(N_NODES + 255) / 256, 256>>>();
    histogram<<<(N_EDGES + 255) / 256, 256>>>(row);
    scan_blocks<<<SCAN_NB, SCAN_BLK>>>();
    scan_sums<<<1, 32>>>();
    add_offsets<<<SCAN_NB, SCAN_BLK>>>();
    fill_csr<<<(N_EDGES + 255) / 256, 256>>>(row, col, ew);

    // --- Weight bf16 hi/lo split (row-major [K][N], no transpose) ---
    split_w<<<(D_IN * D_HID + 255) / 256, 256>>>(w1, w1hi, w1lo, D_IN * D_HID);
    split_w<<<(D_HID * D_OUT + 255) / 256, 256>>>(w2, w2hi, w2lo, D_HID * D_OUT);

    const int MTILES = (N_NODES + 127) / 128;  // 782

    // --- Layer 1: support1 = x @ w1 (WMMA bf16, 3-pass compensated) ---
    gemm_wmma<D_IN, D_HID, 128><<<dim3(D_HID / 128, MTILES), 256>>>(
        x, w1hi, w1lo, sup1, N_NODES);
    // agg1 = relu(segment_sum(ew * sup1[col]) + b1)
    spmm1_csr<<<(N_NODES * 32 + 255) / 256, 256>>>(sup1, b1, agg1);

    // --- Layer 2: support2 = agg1 @ w2 (WMMA bf16, 3-pass compensated) ---
    gemm_wmma<D_HID, D_OUT, 64><<<dim3(1, MTILES), 256>>>(
        agg1, w2hi, w2lo, sup2, N_NODES);
    // out = log_softmax(segment_sum(ew * sup2[col]) + b2)
    spmm2_lsm<<<(N_NODES * 32 + 255) / 256, 256>>>(sup2, b2, out);
}